// round 1
// baseline (speedup 1.0000x reference)
#include <cuda_runtime.h>
#include <cuda_bf16.h>
#include <cstdint>

#define NEG_INF (-1e9f)
#define KDIM 1024
#define NCOLS 288            // 128 q | 128 k | 9 u | pad -> 288
#define XS_STRIDE 72         // 64 + 8 pad (bf16 elems)
#define WS_STRIDE 296        // 288 + 8 pad (bf16 elems)
#define QK_STRIDE 264        // 256 + 8 pad (bf16 elems)
#define LG_STRIDE 68         // 64 + 4 pad (f32)
#define U_STRIDE 12
#define CHUNK 64
#define NCHUNK 16
#define THREADS 512
#define SMEM_BYTES 112640    // max(mainloop 112640, epilogue 108544)

// smem layout (aliased):
//   mainloop: Xs [2][128][72] bf16 @0 (36864B), Ws [2][64][296] bf16 @36864 (75776B)
//   epilogue: QK [128][264] bf16 @0 (67584B), U [128][12] f32 @67584 (6144B),
//             LG [2][64][68] f32 @73728 (34816B)

__device__ __nv_bfloat16 g_W[KDIM * NCOLS];

__constant__ int c_ddr[8] = {1, 1, 0, -1, -1, -1, 0, 1};
__constant__ int c_ddc[8] = {0, 1, 1, 1, 0, -1, -1, -1};
__constant__ int c_kdr[8] = {2, 1, -1, -2, -2, -1, 1, 2};
__constant__ int c_kdc[8] = {1, 2, 2, 1, -1, -2, -2, -1};

__global__ void prep_w(const float* __restrict__ Wq, const float* __restrict__ Wk,
                       const float* __restrict__ Wu) {
    int k = blockIdx.x;
    int c = threadIdx.x;
    float v;
    if (c < 128)      v = Wq[k * 128 + c];
    else if (c < 256) v = Wk[k * 128 + (c - 128)];
    else if (c < 265) v = Wu[k * 9 + (c - 256)];
    else              v = 0.0f;
    g_W[k * NCOLS + c] = __float2bfloat16(v);
}

__device__ __forceinline__ uint32_t smem_u32(const void* p) {
    return (uint32_t)__cvta_generic_to_shared(p);
}
__device__ __forceinline__ uint32_t pack2(float a, float b) {
    __nv_bfloat162 h = __floats2bfloat162_rn(a, b);
    return *reinterpret_cast<uint32_t*>(&h);
}
__device__ __forceinline__ void ldsm_x4(uint32_t& r0, uint32_t& r1, uint32_t& r2, uint32_t& r3, uint32_t a) {
    asm volatile("ldmatrix.sync.aligned.m8n8.x4.shared.b16 {%0,%1,%2,%3}, [%4];"
                 : "=r"(r0), "=r"(r1), "=r"(r2), "=r"(r3) : "r"(a));
}
__device__ __forceinline__ void ldsm_x2(uint32_t& r0, uint32_t& r1, uint32_t a) {
    asm volatile("ldmatrix.sync.aligned.m8n8.x2.shared.b16 {%0,%1}, [%2];"
                 : "=r"(r0), "=r"(r1) : "r"(a));
}
__device__ __forceinline__ void ldsm_x2t(uint32_t& r0, uint32_t& r1, uint32_t a) {
    asm volatile("ldmatrix.sync.aligned.m8n8.x2.trans.shared.b16 {%0,%1}, [%2];"
                 : "=r"(r0), "=r"(r1) : "r"(a));
}
__device__ __forceinline__ void mma_bf16(float* d, const uint32_t* a, const uint32_t* b) {
    asm volatile(
        "mma.sync.aligned.m16n8k16.row.col.f32.bf16.bf16.f32 "
        "{%0,%1,%2,%3}, {%4,%5,%6,%7}, {%8,%9}, {%0,%1,%2,%3};"
        : "+f"(d[0]), "+f"(d[1]), "+f"(d[2]), "+f"(d[3])
        : "r"(a[0]), "r"(a[1]), "r"(a[2]), "r"(a[3]), "r"(b[0]), "r"(b[1]));
}
__device__ __forceinline__ void cp_async16(uint32_t dst, const void* src) {
    asm volatile("cp.async.cg.shared.global [%0], [%1], 16;" :: "r"(dst), "l"(src));
}

extern __shared__ char smem[];

__global__ void __launch_bounds__(THREADS, 1)
policy_kernel(const float* __restrict__ x,
              const float* __restrict__ bq, const float* __restrict__ bk,
              const float* __restrict__ bu, float* __restrict__ out) {
    __nv_bfloat16* Xs = (__nv_bfloat16*)smem;            // [2][128][XS_STRIDE]
    __nv_bfloat16* Ws = (__nv_bfloat16*)(smem + 36864);  // [2][64][WS_STRIDE]

    const int t = threadIdx.x;
    const int w = t >> 5, lane = t & 31;
    const int g = lane >> 2, tig = lane & 3;
    const int warp_m = w >> 2, warp_n = w & 3;   // 4x4 warp grid; tile 32 x 72

    const float* xbase = x + (size_t)blockIdx.x * 128 * KDIM;  // 2 boards = 128 contiguous rows

    float acc[2][9][4];
    #pragma unroll
    for (int mt = 0; mt < 2; mt++)
        #pragma unroll
        for (int nt = 0; nt < 9; nt++)
            #pragma unroll
            for (int i = 0; i < 4; i++) acc[mt][nt][i] = 0.0f;

    float4 xr[4];

    auto load_x = [&](int k0) {
        #pragma unroll
        for (int i = 0; i < 4; i++) {
            int idx = t + i * THREADS;
            int row = idx >> 4, c4 = idx & 15;
            xr[i] = *(const float4*)(xbase + (size_t)row * KDIM + k0 + c4 * 4);
        }
    };
    auto store_x = [&](int buf) {
        __nv_bfloat16* Xb = Xs + buf * 128 * XS_STRIDE;
        #pragma unroll
        for (int i = 0; i < 4; i++) {
            int idx = t + i * THREADS;
            int row = idx >> 4, c4 = idx & 15;
            uint2 p;
            p.x = pack2(xr[i].x, xr[i].y);
            p.y = pack2(xr[i].z, xr[i].w);
            *(uint2*)(Xb + row * XS_STRIDE + c4 * 4) = p;
        }
    };
    auto load_w = [&](int k0, int buf) {
        const __nv_bfloat16* src = g_W + (size_t)k0 * NCOLS;
        __nv_bfloat16* Wb = Ws + buf * 64 * WS_STRIDE;
        for (int idx = t; idx < 64 * 36; idx += THREADS) {
            int row = idx / 36, c = idx - row * 36;
            cp_async16(smem_u32(Wb + row * WS_STRIDE + c * 8), src + row * NCOLS + c * 8);
        }
        asm volatile("cp.async.commit_group;");
    };
    auto compute = [&](int buf) {
        const __nv_bfloat16* Xb = Xs + buf * 128 * XS_STRIDE;
        const __nv_bfloat16* Wb = Ws + buf * 64 * WS_STRIDE;
        const int arow = 32 * warp_m;
        #pragma unroll
        for (int ks = 0; ks < 4; ks++) {
            uint32_t afr[2][4];
            #pragma unroll
            for (int mt = 0; mt < 2; mt++) {
                const __nv_bfloat16* ap =
                    Xb + (arow + 16 * mt + (lane & 15)) * XS_STRIDE + ks * 16 + (lane >> 4) * 8;
                ldsm_x4(afr[mt][0], afr[mt][1], afr[mt][2], afr[mt][3], smem_u32(ap));
            }
            #pragma unroll
            for (int nt = 0; nt < 9; nt++) {
                uint32_t bfr[2];
                const __nv_bfloat16* bp =
                    Wb + (ks * 16 + (lane & 15)) * WS_STRIDE + 72 * warp_n + nt * 8;
                ldsm_x2t(bfr[0], bfr[1], smem_u32(bp));
                mma_bf16(acc[0][nt], afr[0], bfr);
                mma_bf16(acc[1][nt], afr[1], bfr);
            }
        }
    };

    // ---- mainloop: 16 K-chunks, double buffered ----
    load_x(0);
    load_w(0, 0);
    store_x(0);
    asm volatile("cp.async.wait_group 0;");
    __syncthreads();
    for (int c = 0; c < NCHUNK; c++) {
        int nb = (c + 1) & 1;
        if (c + 1 < NCHUNK) {
            load_x((c + 1) * CHUNK);
            load_w((c + 1) * CHUNK, nb);
        }
        compute(c & 1);
        if (c + 1 < NCHUNK) {
            store_x(nb);
            asm volatile("cp.async.wait_group 0;");
        }
        __syncthreads();
    }

    // ---- epilogue: q,k -> smem bf16 (+bias), u -> smem f32 ----
    __nv_bfloat16* QK = (__nv_bfloat16*)smem;   // [128][QK_STRIDE]
    float* U  = (float*)(smem + 67584);         // [128][U_STRIDE]
    float* LG = (float*)(smem + 73728);         // [2][64][LG_STRIDE]

    #pragma unroll
    for (int mt = 0; mt < 2; mt++) {
        int r0 = 32 * warp_m + 16 * mt + g;
        #pragma unroll
        for (int nt = 0; nt < 9; nt++) {
            int c0 = 72 * warp_n + 8 * nt + 2 * tig;
            #pragma unroll
            for (int half = 0; half < 2; half++) {
                int row = r0 + 8 * half;
                float v0 = acc[mt][nt][2 * half + 0];
                float v1 = acc[mt][nt][2 * half + 1];
                if (c0 < 256) {
                    float b0 = (c0 < 128) ? bq[c0] : bk[c0 - 128];
                    float b1 = (c0 < 128) ? bq[c0 + 1] : bk[c0 - 127];
                    *(uint32_t*)(QK + row * QK_STRIDE + c0) = pack2(v0 + b0, v1 + b1);
                } else {
                    int uc = c0 - 256;
                    if (uc < 9)     U[row * U_STRIDE + uc] = v0;
                    if (uc + 1 < 9) U[row * U_STRIDE + uc + 1] = v1;
                }
            }
        }
    }
    __syncthreads();

    // ---- logits = (q @ k^T) * SCALE, per board ----
    {
        const int board_l = w >> 3, wl = w & 7;
        const int lm = wl & 3, ln = wl >> 2;
        const int base_row = board_l * 64;
        float a2[4][4];
        #pragma unroll
        for (int nt = 0; nt < 4; nt++)
            #pragma unroll
            for (int i = 0; i < 4; i++) a2[nt][i] = 0.0f;

        #pragma unroll
        for (int ks = 0; ks < 8; ks++) {
            uint32_t afr[4];
            const __nv_bfloat16* ap =
                QK + (base_row + 16 * lm + (lane & 15)) * QK_STRIDE + ks * 16 + (lane >> 4) * 8;
            ldsm_x4(afr[0], afr[1], afr[2], afr[3], smem_u32(ap));
            #pragma unroll
            for (int nt = 0; nt < 4; nt++) {
                uint32_t bfr[2];
                int trow = base_row + 32 * ln + 8 * nt + (lane & 7);
                int tcol = 128 + ks * 16 + ((lane >> 3) & 1) * 8;
                ldsm_x2(bfr[0], bfr[1], smem_u32(QK + trow * QK_STRIDE + tcol));
                mma_bf16(a2[nt], afr, bfr);
            }
        }
        const float SC = 0.08838834764831845f;  // 128^-0.5
        float* L = LG + board_l * 64 * LG_STRIDE;
        #pragma unroll
        for (int nt = 0; nt < 4; nt++) {
            int fr = 16 * lm + g;
            int tc = 32 * ln + 8 * nt + 2 * tig;
            L[fr * LG_STRIDE + tc]           = a2[nt][0] * SC;
            L[fr * LG_STRIDE + tc + 1]       = a2[nt][1] * SC;
            L[(fr + 8) * LG_STRIDE + tc]     = a2[nt][2] * SC;
            L[(fr + 8) * LG_STRIDE + tc + 1] = a2[nt][3] * SC;
        }
    }
    __syncthreads();

    // ---- gather per LC0 plane tables, mask, write ----
    float* outb = out + (size_t)blockIdx.x * 2 * 4672;
    for (int e = t; e < 2 * 4672; e += THREADS) {
        int board_l = e / 4672;
        int rem = e - board_l * 4672;
        int f = rem / 73;
        int p = rem - f * 73;
        float val = NEG_INF;
        if (p < 64) {
            int r = f >> 3, cc = f & 7;
            int nr, nc;
            if (p < 56) {
                int d = p / 7, dist = p - d * 7 + 1;
                nr = r + c_ddr[d] * dist;
                nc = cc + c_ddc[d] * dist;
            } else {
                int i = p - 56;
                nr = r + c_kdr[i];
                nc = cc + c_kdc[i];
            }
            if (((unsigned)nr < 8u) && ((unsigned)nc < 8u))
                val = LG[(board_l * 64 + f) * LG_STRIDE + nr * 8 + nc];
        } else {
            int n = p - 64;
            if ((f >> 3) == 6)
                val = U[(board_l * 64 + f) * U_STRIDE + n] + bu[n];
        }
        outb[e] = val;
    }
}

extern "C" void kernel_launch(void* const* d_in, const int* in_sizes, int n_in,
                              void* d_out, int out_size) {
    const float* x  = (const float*)d_in[0];
    const float* Wq = (const float*)d_in[1];
    const float* bq = (const float*)d_in[2];
    const float* Wk = (const float*)d_in[3];
    const float* bk = (const float*)d_in[4];
    const float* Wu = (const float*)d_in[5];
    const float* bu = (const float*)d_in[6];
    float* out = (float*)d_out;

    cudaFuncSetAttribute(policy_kernel, cudaFuncAttributeMaxDynamicSharedMemorySize, SMEM_BYTES);

    prep_w<<<1024, 288>>>(Wq, Wk, Wu);
    policy_kernel<<<512, THREADS, SMEM_BYTES>>>(x, bq, bk, bu, out);
}